// round 9
// baseline (speedup 1.0000x reference)
#include <cuda_runtime.h>

// out[m][n] = C[m][n] * D[n];  8192 x 8192 f32, row-major.
// Best-known structure (R3): 16384 blocks x 256 threads x 4 float4, loads
// spaced 64 MB apart (spans all HBM channels / both L2 dies), D loaded once
// (stride is a multiple of NR4). Isolated change vs R3: loads use __ldcs
// (evict-first) so zero-reuse C lines don't occupy L2, leaving capacity for
// the store stream's write-coalescing.

static constexpr int NR4    = 2048;                 // float4s per row
static constexpr int STRIDE = 16384 * 256;          // grid * block = 4,194,304

__global__ __launch_bounds__(256, 6)
void colscale_kernel(const float4* __restrict__ C,
                     const float4* __restrict__ D,
                     float4* __restrict__ out)
{
    const int i = blockIdx.x * 256 + threadIdx.x;   // 0 .. 4,194,303

    // STRIDE % NR4 == 0 -> column index identical across the 4 elements.
    const float4 d = __ldg(&D[i & (NR4 - 1)]);

    const int i0 = i;
    const int i1 = i + STRIDE;
    const int i2 = i + 2 * STRIDE;
    const int i3 = i + 3 * STRIDE;

    // Front-batched evict-first loads (MLP=4), 64 MB apart.
    float4 c0 = __ldcs(&C[i0]);
    float4 c1 = __ldcs(&C[i1]);
    float4 c2 = __ldcs(&C[i2]);
    float4 c3 = __ldcs(&C[i3]);

    c0.x *= d.x; c0.y *= d.y; c0.z *= d.z; c0.w *= d.w;
    c1.x *= d.x; c1.y *= d.y; c1.z *= d.z; c1.w *= d.w;
    c2.x *= d.x; c2.y *= d.y; c2.z *= d.z; c2.w *= d.w;
    c3.x *= d.x; c3.y *= d.y; c3.z *= d.z; c3.w *= d.w;

    out[i0] = c0;
    out[i1] = c1;
    out[i2] = c2;
    out[i3] = c3;
}

extern "C" void kernel_launch(void* const* d_in, const int* in_sizes, int n_in,
                              void* d_out, int out_size)
{
    const float4* C = (const float4*)d_in[0];
    const float4* D = (const float4*)d_in[1];
    float4* out     = (float4*)d_out;

    colscale_kernel<<<16384, 256>>>(C, D, out);
}

// round 10
// speedup vs baseline: 1.0242x; 1.0242x over previous
#include <cuda_runtime.h>

// FINAL: out[m][n] = C[m][n] * D[n];  8192 x 8192 f32, row-major.
// Best measured structure (R3, 82.0 us): single-pass, 16384 blocks x 256
// threads x 4 float4 = 16,777,216 float4s. The 4 per-thread accesses are
// spaced STRIDE = 64 MB apart, spreading concurrent requests across all HBM
// channels / both L2 dies. STRIDE % NR4 == 0, so each thread's column index
// is invariant -> D loaded exactly once. Default cache policy (hints tested
// neutral-to-negative in isolation). Pinned at the mixed read+write HBM
// ceiling (~6.5 TB/s, ~81% of spec); compute/occupancy fully slack.

static constexpr int NR4    = 2048;                 // float4s per row
static constexpr int STRIDE = 16384 * 256;          // grid * block = 4,194,304

__global__ __launch_bounds__(256, 6)
void colscale_kernel(const float4* __restrict__ C,
                     const float4* __restrict__ D,
                     float4* __restrict__ out)
{
    const int i = blockIdx.x * 256 + threadIdx.x;   // 0 .. 4,194,303

    // STRIDE is a multiple of NR4, so column index is invariant across the 4.
    const float4 d = __ldg(&D[i & (NR4 - 1)]);

    const int i0 = i;
    const int i1 = i + STRIDE;
    const int i2 = i + 2 * STRIDE;
    const int i3 = i + 3 * STRIDE;

    // Front-batched loads (MLP=4), 64 MB apart.
    float4 c0 = C[i0];
    float4 c1 = C[i1];
    float4 c2 = C[i2];
    float4 c3 = C[i3];

    c0.x *= d.x; c0.y *= d.y; c0.z *= d.z; c0.w *= d.w;
    c1.x *= d.x; c1.y *= d.y; c1.z *= d.z; c1.w *= d.w;
    c2.x *= d.x; c2.y *= d.y; c2.z *= d.z; c2.w *= d.w;
    c3.x *= d.x; c3.y *= d.y; c3.z *= d.z; c3.w *= d.w;

    out[i0] = c0;
    out[i1] = c1;
    out[i2] = c2;
    out[i3] = c3;
}

extern "C" void kernel_launch(void* const* d_in, const int* in_sizes, int n_in,
                              void* d_out, int out_size)
{
    const float4* C = (const float4*)d_in[0];
    const float4* D = (const float4*)d_in[1];
    float4* out     = (float4*)d_out;

    colscale_kernel<<<16384, 256>>>(C, D, out);
}

// round 11
// speedup vs baseline: 1.0258x; 1.0016x over previous
#include <cuda_runtime.h>

// out[m][n] = C[m][n] * D[n];  8192 x 8192 f32, row-major.
// R3 structure (best known, 82.0 us) with ONE isolated change: stores use
// __stwt (st.global.wt, write-through). Hypothesis: bypassing L2 dirty-line
// writeback scheduling delivers the write stream to the DRAM controllers in
// issue order, smoothing the read/write interleave at the controller.
// Everything else identical: 16384 blocks x 256 threads x 4 float4, accesses
// 64 MB apart, D loaded once per thread (STRIDE % NR4 == 0).

static constexpr int NR4    = 2048;                 // float4s per row
static constexpr int STRIDE = 16384 * 256;          // grid * block = 4,194,304

__global__ __launch_bounds__(256, 6)
void colscale_kernel(const float4* __restrict__ C,
                     const float4* __restrict__ D,
                     float4* __restrict__ out)
{
    const int i = blockIdx.x * 256 + threadIdx.x;   // 0 .. 4,194,303

    // STRIDE is a multiple of NR4, so column index is invariant across the 4.
    const float4 d = __ldg(&D[i & (NR4 - 1)]);

    const int i0 = i;
    const int i1 = i + STRIDE;
    const int i2 = i + 2 * STRIDE;
    const int i3 = i + 3 * STRIDE;

    // Front-batched loads (MLP=4), 64 MB apart.
    float4 c0 = C[i0];
    float4 c1 = C[i1];
    float4 c2 = C[i2];
    float4 c3 = C[i3];

    c0.x *= d.x; c0.y *= d.y; c0.z *= d.z; c0.w *= d.w;
    c1.x *= d.x; c1.y *= d.y; c1.z *= d.z; c1.w *= d.w;
    c2.x *= d.x; c2.y *= d.y; c2.z *= d.z; c2.w *= d.w;
    c3.x *= d.x; c3.y *= d.y; c3.z *= d.z; c3.w *= d.w;

    __stwt(&out[i0], c0);
    __stwt(&out[i1], c1);
    __stwt(&out[i2], c2);
    __stwt(&out[i3], c3);
}

extern "C" void kernel_launch(void* const* d_in, const int* in_sizes, int n_in,
                              void* d_out, int out_size)
{
    const float4* C = (const float4*)d_in[0];
    const float4* D = (const float4*)d_in[1];
    float4* out     = (float4*)d_out;

    colscale_kernel<<<16384, 256>>>(C, D, out);
}